// round 11
// baseline (speedup 1.0000x reference)
#include <cuda_runtime.h>
#include <climits>

#define NN 50000
#define NE 800000
#define D  128
#define DE 16
#define LL 2
#define TT 3
#define G4 512   /* 4*D gates */

// ---------------- scratch (device globals; no allocation allowed) ----------------
__device__ __align__(16) float g_W   [LL*D*D];     // evolved W per layer (in-place over passes)
__device__ __align__(16) float g_G0  [LL*D*G4];    // precomputed Wih@x_t + b per pass
__device__ __align__(16) float g_ft  [NN*D];       // nf @ W
__device__ __align__(16) float g_feats[NN*D];      // layer-0 output
__device__ __align__(16) float g_acc [NN*D];       // attention-weighted accumulation
__device__ float g_ssrc[NN];
__device__ float g_sdst[NN];
__device__ int   g_mx  [NN];                       // encoded-float max
__device__ float g_den [NN];
__device__ float g_sc  [NE];                       // score, then reused as exp(score-max)

// monotonic float<->int encoding so atomicMax(int) == max(float)
__device__ __forceinline__ int   encf(float f){ int b=__float_as_int(f); return b>=0 ? b : (b^0x7FFFFFFF); }
__device__ __forceinline__ float decf(int e){ return __int_as_float(e>=0 ? e : (e^0x7FFFFFFF)); }
__device__ __forceinline__ float sigf(float x){ return 1.f/(1.f+expf(-x)); }

// ---------------- LSTM ----------------
__global__ void k_copyW0(const float* __restrict__ W0){
    int i = blockIdx.x*blockDim.x + threadIdx.x;
    if (i < LL*D*D) g_W[i] = W0[i];
}

// G0[l][t][j] = bih+bhh + Wih[l][j,:] . x_t   (x = current g_W[l])
__global__ void k_g0(const float* __restrict__ Wih,
                     const float* __restrict__ bih,
                     const float* __restrict__ bhh){
    int idx = blockIdx.x*blockDim.x + threadIdx.x;      // 131072 = 2*128*512
    int l = idx >> 16;
    int t = (idx >> 9) & (D-1);
    int j = idx & (G4-1);
    const float4* wr = (const float4*)(Wih + ((size_t)l*G4 + j)*D);
    const float4* xr = (const float4*)(g_W + ((size_t)l*D  + t)*D);
    float acc = bih[l*G4+j] + bhh[l*G4+j];
#pragma unroll
    for (int k=0;k<32;k++){
        float4 w = __ldg(wr+k), x = xr[k];
        acc += w.x*x.x + w.y*x.y + w.z*x.z + w.w*x.w;
    }
    g_G0[((size_t)l*D + t)*G4 + j] = acc;
}

// one pass of the 128-step scan; block per layer; 512 threads = one gate each
__global__ void k_scan(const float* __restrict__ Whh){
    int l = blockIdx.x;
    int j = threadIdx.x;                    // 0..511
    __shared__ __align__(16) float hs[D];
    __shared__ float gb[G4];
    float c = 0.f;
    if (j < D) hs[j] = 0.f;
    __syncthreads();
    const float4* wr = (const float4*)(Whh + ((size_t)l*G4 + j)*D);
    const float4* h4 = (const float4*)hs;
    for (int t=0;t<D;t++){
        float acc = g_G0[((size_t)l*D + t)*G4 + j];
#pragma unroll
        for (int k=0;k<32;k++){
            float4 w = __ldg(wr+k);
            float4 h = h4[k];
            acc += w.x*h.x + w.y*h.y + w.z*h.z + w.w*h.w;
        }
        gb[j] = acc;
        __syncthreads();
        if (j < D){
            float gi = sigf(gb[j]);
            float gf = sigf(gb[j+D]);
            float gg = tanhf(gb[j+2*D]);
            float go = sigf(gb[j+3*D]);
            c = gf*c + gi*gg;
            float hn = go*tanhf(c);
            hs[j] = hn;
            g_W[((size_t)l*D + t)*D + j] = hn;   // scan output becomes new W row
        }
        __syncthreads();
    }
}

// ---------------- GAT ----------------
__global__ void k_init(){
    int i = blockIdx.x*blockDim.x + threadIdx.x;   // 6.4M exact
    g_acc[i] = 0.f;
    if (i < NN){ g_mx[i] = INT_MIN; g_den[i] = 0.f; }
}

// s_src / s_dst : one warp per node
__global__ void k_proj(const float* __restrict__ nf, const float* __restrict__ aw){
    int gt = blockIdx.x*blockDim.x + threadIdx.x;
    int node = gt >> 5, lane = gt & 31;
    if (node >= NN) return;
    float4 x  = __ldg((const float4*)(nf + (size_t)node*D) + lane);
    float4 a1 = __ldg((const float4*)(aw) + lane);          // a_src
    float4 a2 = __ldg((const float4*)(aw + D + DE) + lane); // a_dst (offset 144 floats, 16B aligned)
    float ps = x.x*a1.x + x.y*a1.y + x.z*a1.z + x.w*a1.w;
    float pd = x.x*a2.x + x.y*a2.y + x.z*a2.z + x.w*a2.w;
#pragma unroll
    for (int o=16;o;o>>=1){
        ps += __shfl_xor_sync(0xFFFFFFFFu, ps, o);
        pd += __shfl_xor_sync(0xFFFFFFFFu, pd, o);
    }
    if (lane==0){ g_ssrc[node]=ps; g_sdst[node]=pd; }
}

// ft = nf @ W[layer]   (64x128 tile / block, 256 threads, 24KB static smem)
__global__ void k_gemm(const float* __restrict__ A, int layer){
    __shared__ __align__(16) float Ws[32][128];
    __shared__ __align__(16) float As[64][32];
    const float* W = g_W + (size_t)layer*D*D;
    int tid = threadIdx.x;
    int row0 = blockIdx.x*64;
    int tx = tid & 31, ty = tid >> 5;
    float acc[8][4];
#pragma unroll
    for (int r=0;r<8;r++){ acc[r][0]=acc[r][1]=acc[r][2]=acc[r][3]=0.f; }
    for (int kc=0;kc<4;kc++){
        for (int i=tid;i<1024;i+=256){                    // 32x128 W chunk
            int k = i >> 5, c4 = i & 31;
            *(float4*)&Ws[k][c4*4] = __ldg((const float4*)(W + (size_t)(kc*32+k)*D) + c4);
        }
        for (int i=tid;i<512;i+=256){                     // 64x32 A chunk
            int r = i >> 3, c4 = i & 7;
            int gr = row0 + r;
            float4 v = make_float4(0.f,0.f,0.f,0.f);
            if (gr < NN) v = __ldg((const float4*)(A + (size_t)gr*D + kc*32) + c4);
            *(float4*)&As[r][c4*4] = v;
        }
        __syncthreads();
#pragma unroll
        for (int k=0;k<32;k++){
            float4 b = *(float4*)&Ws[k][tx*4];
#pragma unroll
            for (int r=0;r<8;r++){
                float a = As[ty*8+r][k];
                acc[r][0]+=a*b.x; acc[r][1]+=a*b.y; acc[r][2]+=a*b.z; acc[r][3]+=a*b.w;
            }
        }
        __syncthreads();
    }
#pragma unroll
    for (int r=0;r<8;r++){
        int gr = row0 + ty*8 + r;
        if (gr < NN)
            *(float4*)(g_ft + (size_t)gr*D + tx*4) = make_float4(acc[r][0],acc[r][1],acc[r][2],acc[r][3]);
    }
}

// score + segment_max
__global__ void k_escore(const int* __restrict__ src, const int* __restrict__ dst,
                         const float* __restrict__ ef, const float* __restrict__ aw){
    int e = blockIdx.x*blockDim.x + threadIdx.x;
    if (e >= NE) return;
    int s = src[e], d = dst[e];
    float sc = g_ssrc[s] + g_sdst[d];
    const float4* ep = (const float4*)(ef + (size_t)e*DE);
    const float4* ae = (const float4*)(aw + D);       // a_edge, offset 512B
#pragma unroll
    for (int q=0;q<4;q++){
        float4 ev = ep[q], av = __ldg(ae+q);
        sc += ev.x*av.x + ev.y*av.y + ev.z*av.z + ev.w*av.w;
    }
    g_sc[e] = sc;
    atomicMax(&g_mx[d], encf(sc));
}

// exp(score - max) + segment_sum
__global__ void k_eexp(const int* __restrict__ dst){
    int e = blockIdx.x*blockDim.x + threadIdx.x;
    if (e >= NE) return;
    int d = dst[e];
    float ex = expf(g_sc[e] - decf(g_mx[d]));
    g_sc[e] = ex;
    atomicAdd(&g_den[d], ex);
}

// out[dst] += ft[src] * alpha : one warp per edge, float4 vector atomics
__global__ void k_eagg(const int* __restrict__ src, const int* __restrict__ dst){
    int gt = blockIdx.x*blockDim.x + threadIdx.x;
    int e = gt >> 5, lane = gt & 31;
    if (e >= NE) return;
    int s = 0, d = 0; float a = 0.f;
    if (lane == 0){
        s = src[e]; d = dst[e];
        a = g_sc[e] / g_den[d];
    }
    s = __shfl_sync(0xFFFFFFFFu, s, 0);
    d = __shfl_sync(0xFFFFFFFFu, d, 0);
    a = __shfl_sync(0xFFFFFFFFu, a, 0);
    float4 v = __ldg((const float4*)g_ft + (size_t)s*32 + lane);
    v.x*=a; v.y*=a; v.z*=a; v.w*=a;
    atomicAdd((float4*)g_acc + (size_t)d*32 + lane, v);
}

__global__ void k_fin(float* __restrict__ outp){
    int i = blockIdx.x*blockDim.x + threadIdx.x;   // 6.4M exact
    float v = g_acc[i];
    outp[i] = v > 0.f ? v : 0.01f*v;
}

// ---------------- host ----------------
extern "C" void kernel_launch(void* const* d_in, const int* in_sizes, int n_in,
                              void* d_out, int out_size){
    const int*   src    = (const int*)  d_in[0];
    const int*   dst    = (const int*)  d_in[1];
    const float* nfeats = (const float*)d_in[2];
    const float* efeats = (const float*)d_in[3];
    const float* W0     = (const float*)d_in[4];
    const float* Wih    = (const float*)d_in[5];
    const float* Whh    = (const float*)d_in[6];
    const float* bih    = (const float*)d_in[7];
    const float* bhh    = (const float*)d_in[8];
    const float* aw     = (const float*)d_in[9];

    const int t = TT-1;                       // only the last time slice matters
    const int*   src2 = src + (size_t)t*NE;
    const int*   dst2 = dst + (size_t)t*NE;
    const float* nf2  = nfeats + (size_t)t*NN*D;
    const float* ef2  = efeats + (size_t)t*NE*DE;

    void* fp = nullptr;
    cudaGetSymbolAddress(&fp, g_feats);
    float* featsp = (float*)fp;

    // evolve W: 3 sequential passes, both layer chains in each launch
    k_copyW0<<<(LL*D*D+255)/256,256>>>(W0);
    for (int p=0;p<TT;p++){
        k_g0  <<<512,256>>>(Wih, bih, bhh);
        k_scan<<<LL,G4>>>(Whh);
    }

    for (int l=0;l<LL;l++){
        const float* nf = (l==0) ? nf2 : (const float*)featsp;
        float* outbuf   = (l==0) ? featsp : (float*)d_out;
        const float* awl = aw + (size_t)l*(2*D+DE);

        k_init  <<<6250,1024>>>();
        k_proj  <<<6250,256>>>(nf, awl);
        k_gemm  <<<(NN+63)/64,256>>>(nf, l);
        k_escore<<<NE/256,256>>>(src2, dst2, ef2, awl);
        k_eexp  <<<NE/256,256>>>(dst2);
        k_eagg  <<<(NE*32)/256,256>>>(src2, dst2);
        k_fin   <<<6250,1024>>>(outbuf);
    }
}

// round 12
// speedup vs baseline: 1.0014x; 1.0014x over previous
#include <cuda_runtime.h>
#include <climits>

#define NN 50000
#define NE 800000
#define D  128
#define DE 16
#define LL 2
#define TT 3
#define G4 512   /* 4*D gates */

// ---------------- scratch (device globals; no allocation allowed) ----------------
__device__ __align__(16) float g_W   [LL*D*D];     // evolved W per layer (in-place over passes)
__device__ __align__(16) float g_G0  [LL*D*G4];    // precomputed Wih@x_t + b per pass
__device__ __align__(16) float g_ft  [NN*D];       // nf @ W
__device__ __align__(16) float g_feats[NN*D];      // layer-0 output
__device__ __align__(16) float g_acc [NN*D];       // attention-weighted accumulation
__device__ float g_ssrc[NN];
__device__ float g_sdst[NN];
__device__ int   g_mx  [NN];                       // encoded-float max
__device__ float g_den [NN];
__device__ float g_sc  [NE];                       // score, then reused as exp(score-max)

// monotonic float<->int encoding so atomicMax(int) == max(float)
__device__ __forceinline__ int   encf(float f){ int b=__float_as_int(f); return b>=0 ? b : (b^0x7FFFFFFF); }
__device__ __forceinline__ float decf(int e){ return __int_as_float(e>=0 ? e : (e^0x7FFFFFFF)); }
__device__ __forceinline__ float sigf(float x){ return 1.f/(1.f+expf(-x)); }

// ---------------- LSTM ----------------
__global__ void k_copyW0(const float* __restrict__ W0){
    int i = blockIdx.x*blockDim.x + threadIdx.x;
    if (i < LL*D*D) g_W[i] = W0[i];
}

// G0[l][t][j] = bih+bhh + Wih[l][j,:] . x_t   (x = current g_W[l])
__global__ void k_g0(const float* __restrict__ Wih,
                     const float* __restrict__ bih,
                     const float* __restrict__ bhh){
    int idx = blockIdx.x*blockDim.x + threadIdx.x;      // 131072 = 2*128*512
    int l = idx >> 16;
    int t = (idx >> 9) & (D-1);
    int j = idx & (G4-1);
    const float4* wr = (const float4*)(Wih + ((size_t)l*G4 + j)*D);
    const float4* xr = (const float4*)(g_W + ((size_t)l*D  + t)*D);
    float acc = bih[l*G4+j] + bhh[l*G4+j];
#pragma unroll
    for (int k=0;k<32;k++){
        float4 w = __ldg(wr+k), x = xr[k];
        acc += w.x*x.x + w.y*x.y + w.z*x.z + w.w*x.w;
    }
    g_G0[((size_t)l*D + t)*G4 + j] = acc;
}

// one pass of the 128-step scan; block per layer; 512 threads = one gate each
__global__ void k_scan(const float* __restrict__ Whh){
    int l = blockIdx.x;
    int j = threadIdx.x;                    // 0..511
    __shared__ __align__(16) float hs[D];
    __shared__ float gb[G4];
    float c = 0.f;
    if (j < D) hs[j] = 0.f;
    __syncthreads();
    const float4* wr = (const float4*)(Whh + ((size_t)l*G4 + j)*D);
    const float4* h4 = (const float4*)hs;
    for (int t=0;t<D;t++){
        float acc = g_G0[((size_t)l*D + t)*G4 + j];
#pragma unroll
        for (int k=0;k<32;k++){
            float4 w = __ldg(wr+k);
            float4 h = h4[k];
            acc += w.x*h.x + w.y*h.y + w.z*h.z + w.w*h.w;
        }
        gb[j] = acc;
        __syncthreads();
        if (j < D){
            float gi = sigf(gb[j]);
            float gf = sigf(gb[j+D]);
            float gg = tanhf(gb[j+2*D]);
            float go = sigf(gb[j+3*D]);
            c = gf*c + gi*gg;
            float hn = go*tanhf(c);
            hs[j] = hn;
            g_W[((size_t)l*D + t)*D + j] = hn;   // scan output becomes new W row
        }
        __syncthreads();
    }
}

// ---------------- GAT ----------------
__global__ void k_init(){
    int i = blockIdx.x*blockDim.x + threadIdx.x;   // 6.4M exact
    g_acc[i] = 0.f;
    if (i < NN){ g_mx[i] = INT_MIN; g_den[i] = 0.f; }
}

// s_src / s_dst : one warp per node
__global__ void k_proj(const float* __restrict__ nf, const float* __restrict__ aw){
    int gt = blockIdx.x*blockDim.x + threadIdx.x;
    int node = gt >> 5, lane = gt & 31;
    if (node >= NN) return;
    float4 x  = __ldg((const float4*)(nf + (size_t)node*D) + lane);
    float4 a1 = __ldg((const float4*)(aw) + lane);          // a_src
    float4 a2 = __ldg((const float4*)(aw + D + DE) + lane); // a_dst (offset 144 floats, 16B aligned)
    float ps = x.x*a1.x + x.y*a1.y + x.z*a1.z + x.w*a1.w;
    float pd = x.x*a2.x + x.y*a2.y + x.z*a2.z + x.w*a2.w;
#pragma unroll
    for (int o=16;o;o>>=1){
        ps += __shfl_xor_sync(0xFFFFFFFFu, ps, o);
        pd += __shfl_xor_sync(0xFFFFFFFFu, pd, o);
    }
    if (lane==0){ g_ssrc[node]=ps; g_sdst[node]=pd; }
}

// ft = nf @ W[layer]   (64x128 tile / block, 256 threads, 24KB static smem)
__global__ void k_gemm(const float* __restrict__ A, int layer){
    __shared__ __align__(16) float Ws[32][128];
    __shared__ __align__(16) float As[64][32];
    const float* W = g_W + (size_t)layer*D*D;
    int tid = threadIdx.x;
    int row0 = blockIdx.x*64;
    int tx = tid & 31, ty = tid >> 5;
    float acc[8][4];
#pragma unroll
    for (int r=0;r<8;r++){ acc[r][0]=acc[r][1]=acc[r][2]=acc[r][3]=0.f; }
    for (int kc=0;kc<4;kc++){
        for (int i=tid;i<1024;i+=256){                    // 32x128 W chunk
            int k = i >> 5, c4 = i & 31;
            *(float4*)&Ws[k][c4*4] = __ldg((const float4*)(W + (size_t)(kc*32+k)*D) + c4);
        }
        for (int i=tid;i<512;i+=256){                     // 64x32 A chunk
            int r = i >> 3, c4 = i & 7;
            int gr = row0 + r;
            float4 v = make_float4(0.f,0.f,0.f,0.f);
            if (gr < NN) v = __ldg((const float4*)(A + (size_t)gr*D + kc*32) + c4);
            *(float4*)&As[r][c4*4] = v;
        }
        __syncthreads();
#pragma unroll
        for (int k=0;k<32;k++){
            float4 b = *(float4*)&Ws[k][tx*4];
#pragma unroll
            for (int r=0;r<8;r++){
                float a = As[ty*8+r][k];
                acc[r][0]+=a*b.x; acc[r][1]+=a*b.y; acc[r][2]+=a*b.z; acc[r][3]+=a*b.w;
            }
        }
        __syncthreads();
    }
#pragma unroll
    for (int r=0;r<8;r++){
        int gr = row0 + ty*8 + r;
        if (gr < NN)
            *(float4*)(g_ft + (size_t)gr*D + tx*4) = make_float4(acc[r][0],acc[r][1],acc[r][2],acc[r][3]);
    }
}

// score + segment_max
__global__ void k_escore(const int* __restrict__ src, const int* __restrict__ dst,
                         const float* __restrict__ ef, const float* __restrict__ aw){
    int e = blockIdx.x*blockDim.x + threadIdx.x;
    if (e >= NE) return;
    int s = src[e], d = dst[e];
    float sc = g_ssrc[s] + g_sdst[d];
    const float4* ep = (const float4*)(ef + (size_t)e*DE);
    const float4* ae = (const float4*)(aw + D);       // a_edge, offset 512B
#pragma unroll
    for (int q=0;q<4;q++){
        float4 ev = ep[q], av = __ldg(ae+q);
        sc += ev.x*av.x + ev.y*av.y + ev.z*av.z + ev.w*av.w;
    }
    g_sc[e] = sc;
    atomicMax(&g_mx[d], encf(sc));
}

// exp(score - max) + segment_sum
__global__ void k_eexp(const int* __restrict__ dst){
    int e = blockIdx.x*blockDim.x + threadIdx.x;
    if (e >= NE) return;
    int d = dst[e];
    float ex = expf(g_sc[e] - decf(g_mx[d]));
    g_sc[e] = ex;
    atomicAdd(&g_den[d], ex);
}

// out[dst] += ft[src] * alpha : one warp per edge, float4 vector atomics
__global__ void k_eagg(const int* __restrict__ src, const int* __restrict__ dst){
    int gt = blockIdx.x*blockDim.x + threadIdx.x;
    int e = gt >> 5, lane = gt & 31;
    if (e >= NE) return;
    int s = 0, d = 0; float a = 0.f;
    if (lane == 0){
        s = src[e]; d = dst[e];
        a = g_sc[e] / g_den[d];
    }
    s = __shfl_sync(0xFFFFFFFFu, s, 0);
    d = __shfl_sync(0xFFFFFFFFu, d, 0);
    a = __shfl_sync(0xFFFFFFFFu, a, 0);
    float4 v = __ldg((const float4*)g_ft + (size_t)s*32 + lane);
    v.x*=a; v.y*=a; v.z*=a; v.w*=a;
    atomicAdd((float4*)g_acc + (size_t)d*32 + lane, v);
}

__global__ void k_fin(float* __restrict__ outp){
    int i = blockIdx.x*blockDim.x + threadIdx.x;   // 6.4M exact
    float v = g_acc[i];
    outp[i] = v > 0.f ? v : 0.01f*v;
}

// ---------------- host ----------------
extern "C" void kernel_launch(void* const* d_in, const int* in_sizes, int n_in,
                              void* d_out, int out_size){
    const int*   src    = (const int*)  d_in[0];
    const int*   dst    = (const int*)  d_in[1];
    const float* nfeats = (const float*)d_in[2];
    const float* efeats = (const float*)d_in[3];
    const float* W0     = (const float*)d_in[4];
    const float* Wih    = (const float*)d_in[5];
    const float* Whh    = (const float*)d_in[6];
    const float* bih    = (const float*)d_in[7];
    const float* bhh    = (const float*)d_in[8];
    const float* aw     = (const float*)d_in[9];

    const int t = TT-1;                       // only the last time slice matters
    const int*   src2 = src + (size_t)t*NE;
    const int*   dst2 = dst + (size_t)t*NE;
    const float* nf2  = nfeats + (size_t)t*NN*D;
    const float* ef2  = efeats + (size_t)t*NE*DE;

    void* fp = nullptr;
    cudaGetSymbolAddress(&fp, g_feats);
    float* featsp = (float*)fp;

    // evolve W: 3 sequential passes, both layer chains in each launch
    k_copyW0<<<(LL*D*D+255)/256,256>>>(W0);
    for (int p=0;p<TT;p++){
        k_g0  <<<512,256>>>(Wih, bih, bhh);
        k_scan<<<LL,G4>>>(Whh);
    }

    for (int l=0;l<LL;l++){
        const float* nf = (l==0) ? nf2 : (const float*)featsp;
        float* outbuf   = (l==0) ? featsp : (float*)d_out;
        const float* awl = aw + (size_t)l*(2*D+DE);

        k_init  <<<6250,1024>>>();
        k_proj  <<<6250,256>>>(nf, awl);
        k_gemm  <<<(NN+63)/64,256>>>(nf, l);
        k_escore<<<NE/256,256>>>(src2, dst2, ef2, awl);
        k_eexp  <<<NE/256,256>>>(dst2);
        k_eagg  <<<(NE*32)/256,256>>>(src2, dst2);
        k_fin   <<<6250,1024>>>(outbuf);
    }
}

// round 13
// speedup vs baseline: 1.0023x; 1.0009x over previous
#include <cuda_runtime.h>
#include <climits>

#define NN 50000
#define NE 800000
#define D  128
#define DE 16
#define LL 2
#define TT 3
#define G4 512   /* 4*D gates */

// ---------------- scratch (device globals; no allocation allowed) ----------------
__device__ __align__(16) float g_W   [LL*D*D];     // evolved W per layer (in-place over passes)
__device__ __align__(16) float g_G0  [LL*D*G4];    // precomputed Wih@x_t + b per pass
__device__ __align__(16) float g_ft  [NN*D];       // nf @ W
__device__ __align__(16) float g_feats[NN*D];      // layer-0 output
__device__ __align__(16) float g_acc [NN*D];       // attention-weighted accumulation
__device__ float g_ssrc[NN];
__device__ float g_sdst[NN];
__device__ int   g_mx  [NN];                       // encoded-float max
__device__ float g_den [NN];
__device__ float g_sc  [NE];                       // score, then reused as exp(score-max)

// monotonic float<->int encoding so atomicMax(int) == max(float)
__device__ __forceinline__ int   encf(float f){ int b=__float_as_int(f); return b>=0 ? b : (b^0x7FFFFFFF); }
__device__ __forceinline__ float decf(int e){ return __int_as_float(e>=0 ? e : (e^0x7FFFFFFF)); }
__device__ __forceinline__ float sigf(float x){ return 1.f/(1.f+expf(-x)); }

// ---------------- LSTM ----------------
__global__ void k_copyW0(const float* __restrict__ W0){
    int i = blockIdx.x*blockDim.x + threadIdx.x;
    if (i < LL*D*D) g_W[i] = W0[i];
}

// G0[l][t][j] = bih+bhh + Wih[l][j,:] . x_t   (x = current g_W[l])
__global__ void k_g0(const float* __restrict__ Wih,
                     const float* __restrict__ bih,
                     const float* __restrict__ bhh){
    int idx = blockIdx.x*blockDim.x + threadIdx.x;      // 131072 = 2*128*512
    int l = idx >> 16;
    int t = (idx >> 9) & (D-1);
    int j = idx & (G4-1);
    const float4* wr = (const float4*)(Wih + ((size_t)l*G4 + j)*D);
    const float4* xr = (const float4*)(g_W + ((size_t)l*D  + t)*D);
    float acc = bih[l*G4+j] + bhh[l*G4+j];
#pragma unroll
    for (int k=0;k<32;k++){
        float4 w = __ldg(wr+k), x = xr[k];
        acc += w.x*x.x + w.y*x.y + w.z*x.z + w.w*x.w;
    }
    g_G0[((size_t)l*D + t)*G4 + j] = acc;
}

// one pass of the 128-step scan; block per layer; 512 threads = one gate each
__global__ void k_scan(const float* __restrict__ Whh){
    int l = blockIdx.x;
    int j = threadIdx.x;                    // 0..511
    __shared__ __align__(16) float hs[D];
    __shared__ float gb[G4];
    float c = 0.f;
    if (j < D) hs[j] = 0.f;
    __syncthreads();
    const float4* wr = (const float4*)(Whh + ((size_t)l*G4 + j)*D);
    const float4* h4 = (const float4*)hs;
    for (int t=0;t<D;t++){
        float acc = g_G0[((size_t)l*D + t)*G4 + j];
#pragma unroll
        for (int k=0;k<32;k++){
            float4 w = __ldg(wr+k);
            float4 h = h4[k];
            acc += w.x*h.x + w.y*h.y + w.z*h.z + w.w*h.w;
        }
        gb[j] = acc;
        __syncthreads();
        if (j < D){
            float gi = sigf(gb[j]);
            float gf = sigf(gb[j+D]);
            float gg = tanhf(gb[j+2*D]);
            float go = sigf(gb[j+3*D]);
            c = gf*c + gi*gg;
            float hn = go*tanhf(c);
            hs[j] = hn;
            g_W[((size_t)l*D + t)*D + j] = hn;   // scan output becomes new W row
        }
        __syncthreads();
    }
}

// ---------------- GAT ----------------
__global__ void k_init(){
    int i = blockIdx.x*blockDim.x + threadIdx.x;   // 6.4M exact
    g_acc[i] = 0.f;
    if (i < NN){ g_mx[i] = INT_MIN; g_den[i] = 0.f; }
}

// s_src / s_dst : one warp per node
__global__ void k_proj(const float* __restrict__ nf, const float* __restrict__ aw){
    int gt = blockIdx.x*blockDim.x + threadIdx.x;
    int node = gt >> 5, lane = gt & 31;
    if (node >= NN) return;
    float4 x  = __ldg((const float4*)(nf + (size_t)node*D) + lane);
    float4 a1 = __ldg((const float4*)(aw) + lane);          // a_src
    float4 a2 = __ldg((const float4*)(aw + D + DE) + lane); // a_dst (offset 144 floats, 16B aligned)
    float ps = x.x*a1.x + x.y*a1.y + x.z*a1.z + x.w*a1.w;
    float pd = x.x*a2.x + x.y*a2.y + x.z*a2.z + x.w*a2.w;
#pragma unroll
    for (int o=16;o;o>>=1){
        ps += __shfl_xor_sync(0xFFFFFFFFu, ps, o);
        pd += __shfl_xor_sync(0xFFFFFFFFu, pd, o);
    }
    if (lane==0){ g_ssrc[node]=ps; g_sdst[node]=pd; }
}

// ft = nf @ W[layer]   (64x128 tile / block, 256 threads, 24KB static smem)
__global__ void k_gemm(const float* __restrict__ A, int layer){
    __shared__ __align__(16) float Ws[32][128];
    __shared__ __align__(16) float As[64][32];
    const float* W = g_W + (size_t)layer*D*D;
    int tid = threadIdx.x;
    int row0 = blockIdx.x*64;
    int tx = tid & 31, ty = tid >> 5;
    float acc[8][4];
#pragma unroll
    for (int r=0;r<8;r++){ acc[r][0]=acc[r][1]=acc[r][2]=acc[r][3]=0.f; }
    for (int kc=0;kc<4;kc++){
        for (int i=tid;i<1024;i+=256){                    // 32x128 W chunk
            int k = i >> 5, c4 = i & 31;
            *(float4*)&Ws[k][c4*4] = __ldg((const float4*)(W + (size_t)(kc*32+k)*D) + c4);
        }
        for (int i=tid;i<512;i+=256){                     // 64x32 A chunk
            int r = i >> 3, c4 = i & 7;
            int gr = row0 + r;
            float4 v = make_float4(0.f,0.f,0.f,0.f);
            if (gr < NN) v = __ldg((const float4*)(A + (size_t)gr*D + kc*32) + c4);
            *(float4*)&As[r][c4*4] = v;
        }
        __syncthreads();
#pragma unroll
        for (int k=0;k<32;k++){
            float4 b = *(float4*)&Ws[k][tx*4];
#pragma unroll
            for (int r=0;r<8;r++){
                float a = As[ty*8+r][k];
                acc[r][0]+=a*b.x; acc[r][1]+=a*b.y; acc[r][2]+=a*b.z; acc[r][3]+=a*b.w;
            }
        }
        __syncthreads();
    }
#pragma unroll
    for (int r=0;r<8;r++){
        int gr = row0 + ty*8 + r;
        if (gr < NN)
            *(float4*)(g_ft + (size_t)gr*D + tx*4) = make_float4(acc[r][0],acc[r][1],acc[r][2],acc[r][3]);
    }
}

// score + segment_max
__global__ void k_escore(const int* __restrict__ src, const int* __restrict__ dst,
                         const float* __restrict__ ef, const float* __restrict__ aw){
    int e = blockIdx.x*blockDim.x + threadIdx.x;
    if (e >= NE) return;
    int s = src[e], d = dst[e];
    float sc = g_ssrc[s] + g_sdst[d];
    const float4* ep = (const float4*)(ef + (size_t)e*DE);
    const float4* ae = (const float4*)(aw + D);       // a_edge, offset 512B
#pragma unroll
    for (int q=0;q<4;q++){
        float4 ev = ep[q], av = __ldg(ae+q);
        sc += ev.x*av.x + ev.y*av.y + ev.z*av.z + ev.w*av.w;
    }
    g_sc[e] = sc;
    atomicMax(&g_mx[d], encf(sc));
}

// exp(score - max) + segment_sum
__global__ void k_eexp(const int* __restrict__ dst){
    int e = blockIdx.x*blockDim.x + threadIdx.x;
    if (e >= NE) return;
    int d = dst[e];
    float ex = expf(g_sc[e] - decf(g_mx[d]));
    g_sc[e] = ex;
    atomicAdd(&g_den[d], ex);
}

// out[dst] += ft[src] * alpha : one warp per edge, float4 vector atomics
__global__ void k_eagg(const int* __restrict__ src, const int* __restrict__ dst){
    int gt = blockIdx.x*blockDim.x + threadIdx.x;
    int e = gt >> 5, lane = gt & 31;
    if (e >= NE) return;
    int s = 0, d = 0; float a = 0.f;
    if (lane == 0){
        s = src[e]; d = dst[e];
        a = g_sc[e] / g_den[d];
    }
    s = __shfl_sync(0xFFFFFFFFu, s, 0);
    d = __shfl_sync(0xFFFFFFFFu, d, 0);
    a = __shfl_sync(0xFFFFFFFFu, a, 0);
    float4 v = __ldg((const float4*)g_ft + (size_t)s*32 + lane);
    v.x*=a; v.y*=a; v.z*=a; v.w*=a;
    atomicAdd((float4*)g_acc + (size_t)d*32 + lane, v);
}

__global__ void k_fin(float* __restrict__ outp){
    int i = blockIdx.x*blockDim.x + threadIdx.x;   // 6.4M exact
    float v = g_acc[i];
    outp[i] = v > 0.f ? v : 0.01f*v;
}

// ---------------- host ----------------
extern "C" void kernel_launch(void* const* d_in, const int* in_sizes, int n_in,
                              void* d_out, int out_size){
    const int*   src    = (const int*)  d_in[0];
    const int*   dst    = (const int*)  d_in[1];
    const float* nfeats = (const float*)d_in[2];
    const float* efeats = (const float*)d_in[3];
    const float* W0     = (const float*)d_in[4];
    const float* Wih    = (const float*)d_in[5];
    const float* Whh    = (const float*)d_in[6];
    const float* bih    = (const float*)d_in[7];
    const float* bhh    = (const float*)d_in[8];
    const float* aw     = (const float*)d_in[9];

    const int t = TT-1;                       // only the last time slice matters
    const int*   src2 = src + (size_t)t*NE;
    const int*   dst2 = dst + (size_t)t*NE;
    const float* nf2  = nfeats + (size_t)t*NN*D;
    const float* ef2  = efeats + (size_t)t*NE*DE;

    void* fp = nullptr;
    cudaGetSymbolAddress(&fp, g_feats);
    float* featsp = (float*)fp;

    // evolve W: 3 sequential passes, both layer chains in each launch
    k_copyW0<<<(LL*D*D+255)/256,256>>>(W0);
    for (int p=0;p<TT;p++){
        k_g0  <<<512,256>>>(Wih, bih, bhh);
        k_scan<<<LL,G4>>>(Whh);
    }

    for (int l=0;l<LL;l++){
        const float* nf = (l==0) ? nf2 : (const float*)featsp;
        float* outbuf   = (l==0) ? featsp : (float*)d_out;
        const float* awl = aw + (size_t)l*(2*D+DE);

        k_init  <<<6250,1024>>>();
        k_proj  <<<6250,256>>>(nf, awl);
        k_gemm  <<<(NN+63)/64,256>>>(nf, l);
        k_escore<<<NE/256,256>>>(src2, dst2, ef2, awl);
        k_eexp  <<<NE/256,256>>>(dst2);
        k_eagg  <<<(NE*32)/256,256>>>(src2, dst2);
        k_fin   <<<6250,1024>>>(outbuf);
    }
}